// round 15
// baseline (speedup 1.0000x reference)
#include <cuda_runtime.h>
#include <cuda_fp16.h>
#include <math.h>
#include <stdint.h>

// Problem constants
#define NX     768
#define NHEAD  12
#define DH     64
#define NCTX   2048
#define BATCH  4
#define MROWS  (BATCH * NCTX)        // 8192
#define EPS    1e-5f
#define NEGBIG -1000000000.0f
#define LOG2E  1.4426950408889634f

// ---------------- scratch (no allocations allowed) ----------------
__device__ float g_n   [MROWS * NX];
__device__ float g_tmp [MROWS * NX];
__device__ __half g_ahi[MROWS * NX];
__device__ __half g_hhi[MROWS * 4 * NX];   // also holds qkv hi (2304<=3072)
__device__ __half g_hlo[MROWS * 4 * NX];   // also holds qkv lo (Q,K only used)
#define WOFF_ATTN 0
#define WOFF_PROJ (3*NX*NX)
#define WOFF_FC   (WOFF_PROJ + NX*NX)
#define WOFF_FC2  (WOFF_FC + 4*NX*NX)
#define WTOTAL    (WOFF_FC2 + 4*NX*NX)
__device__ __half g_whi[WTOTAL];           // fp16 weights

// =====================================================================
// helpers
// =====================================================================
__device__ __forceinline__ uint32_t smem_u32(const void* p) {
    uint32_t a;
    asm("{ .reg .u64 t; cvta.to.shared.u64 t, %1; cvt.u32.u64 %0, t; }" : "=r"(a) : "l"(p));
    return a;
}
__device__ __forceinline__ void cp_async16(uint32_t s, const void* g) {
    asm volatile("cp.async.cg.shared.global [%0], [%1], 16;\n"
                 :: "r"(s), "l"(__cvta_generic_to_global(g)));
}
#define CP_COMMIT()   asm volatile("cp.async.commit_group;\n" ::: "memory")
#define CP_WAIT(n)    asm volatile("cp.async.wait_group %0;\n" :: "n"(n) : "memory")

__device__ __forceinline__ void ldsm_x4(uint32_t* r, uint32_t addr) {
    asm volatile("ldmatrix.sync.aligned.m8n8.x4.shared.b16 {%0,%1,%2,%3}, [%4];"
                 : "=r"(r[0]), "=r"(r[1]), "=r"(r[2]), "=r"(r[3]) : "r"(addr));
}
__device__ __forceinline__ void ldsm_x4_t(uint32_t* r, uint32_t addr) {
    asm volatile("ldmatrix.sync.aligned.m8n8.x4.trans.shared.b16 {%0,%1,%2,%3}, [%4];"
                 : "=r"(r[0]), "=r"(r[1]), "=r"(r[2]), "=r"(r[3]) : "r"(addr));
}
__device__ __forceinline__ void mma16816(float* d, const uint32_t* a, const uint32_t* b) {
    asm volatile(
        "mma.sync.aligned.m16n8k16.row.col.f32.f16.f16.f32 "
        "{%0,%1,%2,%3}, {%4,%5,%6,%7}, {%8,%9}, {%0,%1,%2,%3};"
        : "+f"(d[0]), "+f"(d[1]), "+f"(d[2]), "+f"(d[3])
        : "r"(a[0]), "r"(a[1]), "r"(a[2]), "r"(a[3]), "r"(b[0]), "r"(b[1]));
}
__device__ __forceinline__ uint32_t pack_h2(float a, float b) {
    __half2 t = __floats2half2_rn(a, b);
    return *reinterpret_cast<uint32_t*>(&t);
}
// hardware exp2 (MUFU.EX2) — single instruction, ~2^-22 rel err
__device__ __forceinline__ float ex2(float x) {
    float r;
    asm("ex2.approx.f32 %0, %1;" : "=f"(r) : "f"(x));
    return r;
}

// =====================================================================
// Pure fp16 HMMA GEMM: C = Ahi @ Whi^T + bias
// Tile 128x128x64 (BK=64), 2 CTAs/SM, 2-stage cp.async (R12 proven).
// lo_cols: columns < lo_cols also emit the fp16 residual.
// [sc_lo, sc_hi): columns scaled by `scale` after bias (log2e fold for K).
// =====================================================================
#define GST    72                          // smem row stride in halves (144B)
#define TILEB  (128 * GST * 2)             // 18432
#define STAGEB (2 * TILEB)                 // 36864 (A + B)
#define GEMM_DSMEM 73728                   // 2 stages

__global__ __launch_bounds__(256, 2) void gemm_tc_kernel(
    const __half* __restrict__ Ahi,
    const __half* __restrict__ Bhi,
    const float* __restrict__ bias,
    float* __restrict__ C, __half* __restrict__ Hhi, __half* __restrict__ Hlo,
    int M, int N, int K, int relu, int lo_cols, int sc_lo, int sc_hi, float scale)
{
    extern __shared__ __align__(16) char dsm[];
    const uint32_t sbase = smem_u32(dsm);

    const int tid  = threadIdx.x;
    const int wid  = tid >> 5;
    const int lane = tid & 31;
    const int wm   = wid >> 2;
    const int wn   = wid & 3;
    const int row0 = blockIdx.y * 128;
    const int col0 = blockIdx.x * 128;

    float acc[4][4][4];
#pragma unroll
    for (int mi = 0; mi < 4; mi++)
#pragma unroll
        for (int ni = 0; ni < 4; ni++)
#pragma unroll
            for (int j = 0; j < 4; j++) acc[mi][ni][j] = 0.0f;

    const int nchunks = K >> 6;

    auto load_stage = [&](int i) {
        const uint32_t st = sbase + (i & 1) * STAGEB;
        const int kt = i << 6;
#pragma unroll 8
        for (int u = tid; u < 2048; u += 256) {
            int t8 = u >> 10;                  // 0: A, 1: B
            int v = u & 1023;
            int r = v >> 3, c = v & 7;
            uint32_t off = (uint32_t)(t8 * TILEB + r * (GST * 2) + c * 16);
            const __half* src = t8 ? (Bhi + (size_t)(col0 + r) * K + kt + c * 8)
                                   : (Ahi + (size_t)(row0 + r) * K + kt + c * 8);
            cp_async16(st + off, src);
        }
        CP_COMMIT();
    };

    load_stage(0);
    if (nchunks > 1) load_stage(1);

    const int lr8 = lane & 7;
    const int lg  = lane >> 3;
    const int a_row = lr8 + (lg & 1) * 8;
    const int a_col = (lg >> 1) * 8;
    const int b_rowg = (lg >> 1) * 8 + lr8;
    const int b_colg = (lg & 1) * 8;

    for (int i = 0; i < nchunks; i++) {
        if (i + 1 < nchunks) CP_WAIT(1); else CP_WAIT(0);
        __syncthreads();

        const uint32_t st  = sbase + (i & 1) * STAGEB;
        const uint32_t sAh = st;
        const uint32_t sBh = st + TILEB;

#pragma unroll
        for (int ks = 0; ks < 4; ks++) {
            const int kc = ks * 16;
            uint32_t bhi[4][2];
#pragma unroll
            for (int p = 0; p < 2; p++) {
                int nrow = wn * 32 + p * 16 + b_rowg;
                uint32_t off = (uint32_t)(nrow * (GST * 2) + (kc + b_colg) * 2);
                uint32_t r4[4];
                ldsm_x4(r4, sBh + off);
                bhi[p*2][0] = r4[0]; bhi[p*2][1] = r4[1];
                bhi[p*2+1][0] = r4[2]; bhi[p*2+1][1] = r4[3];
            }
#pragma unroll
            for (int mi = 0; mi < 4; mi++) {
                int mrow = wm * 64 + mi * 16 + a_row;
                uint32_t off = (uint32_t)(mrow * (GST * 2) + (kc + a_col) * 2);
                uint32_t ah[4];
                ldsm_x4(ah, sAh + off);
#pragma unroll
                for (int ni = 0; ni < 4; ni++)
                    mma16816(acc[mi][ni], ah, bhi[ni]);
            }
        }
        __syncthreads();
        if (i + 2 < nchunks) load_stage(i + 2);
    }

    float* sof = (float*)dsm;
    const int qr = lane >> 2;
    const int qc2 = (lane & 3) * 2;
#pragma unroll
    for (int mi = 0; mi < 4; mi++) {
#pragma unroll
        for (int ni = 0; ni < 4; ni++) {
            int r = wm * 64 + mi * 16 + qr;
            int c = wn * 32 + ni * 8 + qc2;
            *(float2*)(sof + r * 132 + c)       = make_float2(acc[mi][ni][0], acc[mi][ni][1]);
            *(float2*)(sof + (r + 8) * 132 + c) = make_float2(acc[mi][ni][2], acc[mi][ni][3]);
        }
    }
    __syncthreads();

    for (int i = tid; i < 128 * 32; i += 256) {
        int r = i >> 5, cu = i & 31;
        float4 v = *(float4*)(sof + r * 132 + cu * 4);
        int gcol = col0 + cu * 4;
        float4 bb = *(const float4*)(bias + gcol);
        v.x += bb.x; v.y += bb.y; v.z += bb.z; v.w += bb.w;
        if (relu) {
            v.x = fmaxf(v.x, 0.0f); v.y = fmaxf(v.y, 0.0f);
            v.z = fmaxf(v.z, 0.0f); v.w = fmaxf(v.w, 0.0f);
        }
        if (gcol >= sc_lo && gcol < sc_hi) {
            v.x *= scale; v.y *= scale; v.z *= scale; v.w *= scale;
        }
        size_t gi = (size_t)(row0 + r) * N + gcol;
        if (C) *(float4*)(C + gi) = v;
        if (Hhi) {
            __half h0 = __float2half_rn(v.x), h1 = __float2half_rn(v.y);
            __half h2 = __float2half_rn(v.z), h3 = __float2half_rn(v.w);
            __half2 p0; p0.x = h0; p0.y = h1;
            __half2 p1; p1.x = h2; p1.y = h3;
            *(__half2*)(Hhi + gi) = p0;
            *(__half2*)(Hhi + gi + 2) = p1;
            if (Hlo && gcol < lo_cols) {
                __half2 q0, q1;
                q0.x = __float2half_rn(v.x - __half2float(h0));
                q0.y = __float2half_rn(v.y - __half2float(h1));
                q1.x = __float2half_rn(v.z - __half2float(h2));
                q1.y = __float2half_rn(v.w - __half2float(h3));
                *(__half2*)(Hlo + gi) = q0;
                *(__half2*)(Hlo + gi + 2) = q1;
            }
        }
    }
}

// =====================================================================
// HMMA flash attention: QK 3-term, PV 2-term, ex2.approx softmax
// (K pre-scaled by log2e). Double-buffered K/V; heavy tiles first.
// =====================================================================
#define AST    72
#define A_Q_BYTES  (128 * AST * 2)
#define A_KV_BYTES (64 * AST * 2)
#define KVSTAGE    (3 * A_KV_BYTES)
#define SQH 0
#define SQL (A_Q_BYTES)
#define KVBASE (2 * A_Q_BYTES)
#define ATTN_DSMEM (2 * A_Q_BYTES + 2 * KVSTAGE)   // 92160

__global__ __launch_bounds__(256) void attn_mma_kernel(
    const __half* __restrict__ qh_, const __half* __restrict__ ql_,
    __half* __restrict__ ohi_)
{
    extern __shared__ __align__(16) char dsm[];
    const uint32_t sb = smem_u32(dsm);

    const int tid  = threadIdx.x;
    const int wid  = tid >> 5;
    const int lane = tid & 31;
    const int it = (int)gridDim.x - 1 - (int)blockIdx.x;
    const int h  = blockIdx.y;
    const int b  = blockIdx.z;
    const int row0  = it * 128;
    const int grow0 = b * NCTX + row0;

    for (int u = tid; u < 1024; u += 256) {
        int r = u >> 3, c = u & 7;
        uint32_t off = (uint32_t)(r * (AST * 2) + c * 16);
        size_t gi = (size_t)(grow0 + r) * (3 * NX) + h * DH + c * 8;
        cp_async16(sb + SQH + off, qh_ + gi);
        cp_async16(sb + SQL + off, ql_ + gi);
    }
    CP_COMMIT();

    const int wr  = wid * 16;
    const int lr  = lane >> 2;
    const int qc  = lane & 3;
    const int lr8 = lane & 7;
    const int lg  = lane >> 3;
    const int a_row = lr8 + (lg & 1) * 8;
    const int a_col = (lg >> 1) * 8;
    const int b_rowg = (lg >> 1) * 8 + lr8;
    const int b_colg = (lg & 1) * 8;
    const int v_row = (lg & 1) * 8 + lr8;
    const int v_col = (lg >> 1) * 8;

    const int jmax = 2 * it + 1;

    auto load_kv = [&](int jt) {
        const uint32_t st = sb + KVBASE + (jt & 1) * KVSTAGE;
        for (int u = tid; u < 512; u += 256) {
            int r = u >> 3, c = u & 7;
            uint32_t off = (uint32_t)(r * (AST * 2) + c * 16);
            size_t gk = (size_t)(b * NCTX + jt * 64 + r) * (3 * NX) + NX + h * DH + c * 8;
            cp_async16(st + off,                   qh_ + gk);
            cp_async16(st + A_KV_BYTES + off,      ql_ + gk);
            cp_async16(st + 2 * A_KV_BYTES + off,  qh_ + gk + NX);
        }
        CP_COMMIT();
    };

    load_kv(0);
    CP_WAIT(0);
    __syncthreads();

    uint32_t qh[4][4], ql[4][4];
#pragma unroll
    for (int kk = 0; kk < 4; kk++) {
        uint32_t off = (uint32_t)((wr + a_row) * (AST * 2) + (kk * 16 + a_col) * 2);
        ldsm_x4(qh[kk], sb + SQH + off);
        ldsm_x4(ql[kk], sb + SQL + off);
    }

    float m0 = -INFINITY, m1 = -INFINITY, l0 = 0.0f, l1 = 0.0f;
    float o[8][4];
#pragma unroll
    for (int ni = 0; ni < 8; ni++)
#pragma unroll
        for (int e = 0; e < 4; e++) o[ni][e] = 0.0f;

    for (int jt = 0; jt <= jmax; jt++) {
        if (jt + 1 <= jmax) { load_kv(jt + 1); CP_WAIT(1); }
        else                { CP_WAIT(0); }
        __syncthreads();

        const uint32_t st = sb + KVBASE + (jt & 1) * KVSTAGE;
        const uint32_t sKH = st;
        const uint32_t sKL = st + A_KV_BYTES;
        const uint32_t sVH = st + 2 * A_KV_BYTES;

        const int col0 = jt * 64;
        const bool fullmask = col0 > row0 + wr + 15;
        if (!fullmask) {
            float s[8][4];
#pragma unroll
            for (int ni = 0; ni < 8; ni++)
#pragma unroll
                for (int e = 0; e < 4; e++) s[ni][e] = 0.0f;

#pragma unroll
            for (int kk = 0; kk < 4; kk++) {
                uint32_t bh[8][2], bl[8][2];
#pragma unroll
                for (int p = 0; p < 4; p++) {
                    uint32_t off = (uint32_t)((p * 16 + b_rowg) * (AST * 2) + (kk * 16 + b_colg) * 2);
                    uint32_t r4[4];
                    ldsm_x4(r4, sKH + off);
                    bh[p*2][0] = r4[0]; bh[p*2][1] = r4[1];
                    bh[p*2+1][0] = r4[2]; bh[p*2+1][1] = r4[3];
                    ldsm_x4(r4, sKL + off);
                    bl[p*2][0] = r4[0]; bl[p*2][1] = r4[1];
                    bl[p*2+1][0] = r4[2]; bl[p*2+1][1] = r4[3];
                }
#pragma unroll
                for (int ni = 0; ni < 8; ni++) {
                    mma16816(s[ni], qh[kk], bh[ni]);
                    mma16816(s[ni], ql[kk], bh[ni]);
                    mma16816(s[ni], qh[kk], bl[ni]);
                }
            }

            if (col0 + 63 > row0 + wr) {
                const int gr0 = row0 + wr + lr;
#pragma unroll
                for (int ni = 0; ni < 8; ni++) {
                    int gc = col0 + ni * 8 + qc * 2;
                    if (gc > gr0)         s[ni][0] = NEGBIG;
                    if (gc + 1 > gr0)     s[ni][1] = NEGBIG;
                    if (gc > gr0 + 8)     s[ni][2] = NEGBIG;
                    if (gc + 1 > gr0 + 8) s[ni][3] = NEGBIG;
                }
            }

            float mt0 = s[0][0], mt1 = s[0][2];
#pragma unroll
            for (int ni = 0; ni < 8; ni++) {
                mt0 = fmaxf(mt0, fmaxf(s[ni][0], s[ni][1]));
                mt1 = fmaxf(mt1, fmaxf(s[ni][2], s[ni][3]));
            }
            mt0 = fmaxf(mt0, __shfl_xor_sync(0xffffffffu, mt0, 1));
            mt0 = fmaxf(mt0, __shfl_xor_sync(0xffffffffu, mt0, 2));
            mt1 = fmaxf(mt1, __shfl_xor_sync(0xffffffffu, mt1, 1));
            mt1 = fmaxf(mt1, __shfl_xor_sync(0xffffffffu, mt1, 2));
            float mn0 = fmaxf(m0, mt0), mn1 = fmaxf(m1, mt1);
            float al0 = ex2(m0 - mn0), al1 = ex2(m1 - mn1);
            m0 = mn0; m1 = mn1;

            float sum0 = 0.0f, sum1 = 0.0f;
#pragma unroll
            for (int ni = 0; ni < 8; ni++) {
                s[ni][0] = ex2(s[ni][0] - mn0);
                s[ni][1] = ex2(s[ni][1] - mn0);
                s[ni][2] = ex2(s[ni][2] - mn1);
                s[ni][3] = ex2(s[ni][3] - mn1);
                sum0 += s[ni][0] + s[ni][1];
                sum1 += s[ni][2] + s[ni][3];
            }
            sum0 += __shfl_xor_sync(0xffffffffu, sum0, 1);
            sum0 += __shfl_xor_sync(0xffffffffu, sum0, 2);
            sum1 += __shfl_xor_sync(0xffffffffu, sum1, 1);
            sum1 += __shfl_xor_sync(0xffffffffu, sum1, 2);
            l0 = l0 * al0 + sum0;
            l1 = l1 * al1 + sum1;

#pragma unroll
            for (int ni = 0; ni < 8; ni++) {
                o[ni][0] *= al0; o[ni][1] *= al0;
                o[ni][2] *= al1; o[ni][3] *= al1;
            }

#pragma unroll
            for (int kk = 0; kk < 4; kk++) {
                uint32_t pa_h[4], pa_l[4];
                {
                    float p00 = s[2*kk][0],   p01 = s[2*kk][1];
                    float p10 = s[2*kk][2],   p11 = s[2*kk][3];
                    float p20 = s[2*kk+1][0], p21 = s[2*kk+1][1];
                    float p30 = s[2*kk+1][2], p31 = s[2*kk+1][3];
                    pa_h[0] = pack_h2(p00, p01);
                    pa_h[1] = pack_h2(p10, p11);
                    pa_h[2] = pack_h2(p20, p21);
                    pa_h[3] = pack_h2(p30, p31);
                    __half2 t;
                    t = *(__half2*)&pa_h[0];
                    pa_l[0] = pack_h2(p00 - __half2float(t.x), p01 - __half2float(t.y));
                    t = *(__half2*)&pa_h[1];
                    pa_l[1] = pack_h2(p10 - __half2float(t.x), p11 - __half2float(t.y));
                    t = *(__half2*)&pa_h[2];
                    pa_l[2] = pack_h2(p20 - __half2float(t.x), p21 - __half2float(t.y));
                    t = *(__half2*)&pa_h[3];
                    pa_l[3] = pack_h2(p30 - __half2float(t.x), p31 - __half2float(t.y));
                }
                uint32_t vh[8][2];
#pragma unroll
                for (int p = 0; p < 4; p++) {
                    uint32_t off = (uint32_t)((kk * 16 + v_row) * (AST * 2) + (p * 16 + v_col) * 2);
                    uint32_t r4[4];
                    ldsm_x4_t(r4, sVH + off);
                    vh[p*2][0] = r4[0]; vh[p*2][1] = r4[1];
                    vh[p*2+1][0] = r4[2]; vh[p*2+1][1] = r4[3];
                }
#pragma unroll
                for (int ni = 0; ni < 8; ni++) {
                    mma16816(o[ni], pa_h, vh[ni]);
                    mma16816(o[ni], pa_l, vh[ni]);
                }
            }
        }
        __syncthreads();
    }

    const float inv0 = 1.0f / l0, inv1 = 1.0f / l1;
    const int gr = grow0 + wr + lr;
    const int gcb = h * DH + qc * 2;
#pragma unroll
    for (int ni = 0; ni < 8; ni++) {
        float v0 = o[ni][0] * inv0, v1 = o[ni][1] * inv0;
        float v2 = o[ni][2] * inv1, v3 = o[ni][3] * inv1;
        size_t i0 = (size_t)gr * NX + gcb + ni * 8;
        size_t i1 = (size_t)(gr + 8) * NX + gcb + ni * 8;
        *(uint32_t*)(ohi_ + i0) = pack_h2(v0, v1);
        *(uint32_t*)(ohi_ + i1) = pack_h2(v2, v3);
    }
}

// =====================================================================
// weight transpose (fp16)
// =====================================================================
__global__ __launch_bounds__(256) void tsplit_kernel(
    const float* __restrict__ W, __half* __restrict__ hi, int K, int N)
{
    __shared__ float t[32][33];
    const int n0 = blockIdx.x * 32, k0 = blockIdx.y * 32;
    const int tx = threadIdx.x & 31, ty = threadIdx.x >> 5;
#pragma unroll
    for (int i = 0; i < 32; i += 8)
        t[ty + i][tx] = W[(size_t)(k0 + ty + i) * N + n0 + tx];
    __syncthreads();
#pragma unroll
    for (int i = 0; i < 32; i += 8) {
        float v = t[tx][ty + i];
        hi[(size_t)(n0 + ty + i) * K + k0 + tx] = __float2half_rn(v);
    }
}

__global__ __launch_bounds__(256) void split_kernel(
    const float* __restrict__ in, __half* __restrict__ hi, int n4)
{
    int i = blockIdx.x * blockDim.x + threadIdx.x;
    if (i >= n4) return;
    float4 v = *(const float4*)(in + i * 4);
    __half2 p0 = __floats2half2_rn(v.x, v.y);
    __half2 p1 = __floats2half2_rn(v.z, v.w);
    *(__half2*)(hi + i * 4) = p0;
    *(__half2*)(hi + i * 4 + 2) = p1;
}

// =====================================================================
// LayerNorm (additive, faithful to source bug) + optional fp16 out
// =====================================================================
__global__ __launch_bounds__(256) void ln_kernel(
    const float* __restrict__ in1, const float* __restrict__ in2,
    const float* __restrict__ g, const float* __restrict__ bb,
    float* __restrict__ out, __half* __restrict__ ohi)
{
    __shared__ float buf[NX];
    __shared__ float wsum[8], wsum2[8];

    const int row = blockIdx.x;
    const int tid = threadIdx.x;
    const int lane = tid & 31;
    const int wrp = tid >> 5;
    const size_t base = (size_t)row * NX;

    float s = 0.0f, s2 = 0.0f;
#pragma unroll
    for (int k = 0; k < 3; k++) {
        int i = tid + k * 256;
        float v = in1[base + i] + in2[base + i];
        buf[i] = v;
        s += v; s2 += v * v;
    }
#pragma unroll
    for (int off = 16; off > 0; off >>= 1) {
        s  += __shfl_xor_sync(0xffffffffu, s,  off);
        s2 += __shfl_xor_sync(0xffffffffu, s2, off);
    }
    if (lane == 0) { wsum[wrp] = s; wsum2[wrp] = s2; }
    __syncthreads();
    if (wrp == 0) {
        float a = (lane < 8) ? wsum[lane] : 0.0f;
        float a2 = (lane < 8) ? wsum2[lane] : 0.0f;
#pragma unroll
        for (int off = 4; off > 0; off >>= 1) {
            a  += __shfl_xor_sync(0xffffffffu, a,  off);
            a2 += __shfl_xor_sync(0xffffffffu, a2, off);
        }
        if (lane == 0) { wsum[0] = a; wsum2[0] = a2; }
    }
    __syncthreads();
    const float u = wsum[0] * (1.0f / NX);
    const float var = wsum2[0] * (1.0f / NX) - u * u;
    const float rstd = rsqrtf(var + EPS);
#pragma unroll
    for (int k = 0; k < 3; k++) {
        int i = tid + k * 256;
        float v = g[i] + (buf[i] - u) * rstd + bb[i];
        out[base + i] = v;
        if (ohi) ohi[base + i] = __float2half_rn(v);
    }
}

// =====================================================================
extern "C" void kernel_launch(void* const* d_in, const int* in_sizes, int n_in,
                              void* d_out, int out_size)
{
    const float* x      = (const float*)d_in[0];
    const float* w_attn = (const float*)d_in[1];
    const float* b_attn = (const float*)d_in[2];
    const float* w_proj = (const float*)d_in[3];
    const float* b_proj = (const float*)d_in[4];
    const float* ln1_g  = (const float*)d_in[5];
    const float* ln1_b  = (const float*)d_in[6];
    const float* w_fc   = (const float*)d_in[7];
    const float* b_fc   = (const float*)d_in[8];
    const float* w_fc2  = (const float*)d_in[9];
    const float* b_fc2  = (const float*)d_in[10];
    const float* ln2_g  = (const float*)d_in[11];
    const float* ln2_b  = (const float*)d_in[12];
    float* out = (float*)d_out;

    float *nbuf, *tmp;
    __half *ahi, *hhi, *hlo, *whi;
    cudaGetSymbolAddress((void**)&nbuf, g_n);
    cudaGetSymbolAddress((void**)&tmp,  g_tmp);
    cudaGetSymbolAddress((void**)&ahi,  g_ahi);
    cudaGetSymbolAddress((void**)&hhi,  g_hhi);
    cudaGetSymbolAddress((void**)&hlo,  g_hlo);
    cudaGetSymbolAddress((void**)&whi,  g_whi);

    static int smem_set = 0;
    if (!smem_set) {
        cudaFuncSetAttribute(gemm_tc_kernel,
                             cudaFuncAttributeMaxDynamicSharedMemorySize, GEMM_DSMEM);
        cudaFuncSetAttribute(attn_mma_kernel,
                             cudaFuncAttributeMaxDynamicSharedMemorySize, ATTN_DSMEM);
        smem_set = 1;
    }

    // --- weight prep (fp16) ---
    tsplit_kernel<<<dim3(3 * NX / 32, NX / 32), 256>>>(w_attn, whi + WOFF_ATTN, NX, 3 * NX);
    tsplit_kernel<<<dim3(NX / 32, NX / 32),     256>>>(w_proj, whi + WOFF_PROJ, NX, NX);
    tsplit_kernel<<<dim3(4 * NX / 32, NX / 32), 256>>>(w_fc,   whi + WOFF_FC,   NX, 4 * NX);
    tsplit_kernel<<<dim3(NX / 32, 4 * NX / 32), 256>>>(w_fc2,  whi + WOFF_FC2,  4 * NX, NX);

    // --- x -> fp16 ---
    split_kernel<<<(MROWS * NX / 4 + 255) / 256, 256>>>(x, ahi, MROWS * NX / 4);

    // 1. qkv = x @ w_attn + b_attn; K cols pre-scaled by log2e; hi + lo(Q,K)
    gemm_tc_kernel<<<dim3(3 * NX / 128, MROWS / 128), 256, GEMM_DSMEM>>>(
        ahi, whi + WOFF_ATTN, b_attn, nullptr, hhi, hlo,
        MROWS, 3 * NX, NX, 0, 2 * NX, NX, 2 * NX, LOG2E);

    // 2. attention (QK 3-term, PV 2-term, ex2 softmax)
    attn_mma_kernel<<<dim3(NCTX / 128, NHEAD, BATCH), 256, ATTN_DSMEM>>>(
        hhi, hlo, ahi);

    // 3. proj = attn @ w_proj + b_proj -> tmp fp32
    gemm_tc_kernel<<<dim3(NX / 128, MROWS / 128), 256, GEMM_DSMEM>>>(
        ahi, whi + WOFF_PROJ, b_proj, tmp, nullptr, nullptr,
        MROWS, NX, NX, 0, 0, 0, 0, 1.0f);

    // 4. n = LN(x + proj) -> nbuf fp32 + ahi fp16
    ln_kernel<<<MROWS, 256>>>(x, tmp, ln1_g, ln1_b, nbuf, ahi);

    // 5. h = relu(n @ w_fc + b_fc) -> hhi fp16 only
    gemm_tc_kernel<<<dim3(4 * NX / 128, MROWS / 128), 256, GEMM_DSMEM>>>(
        ahi, whi + WOFF_FC, b_fc, nullptr, hhi, nullptr,
        MROWS, 4 * NX, NX, 1, 0, 0, 0, 1.0f);

    // 6. m = h @ w_fc2 + b_fc2 -> tmp
    gemm_tc_kernel<<<dim3(NX / 128, MROWS / 128), 256, GEMM_DSMEM>>>(
        hhi, whi + WOFF_FC2, b_fc2, tmp, nullptr, nullptr,
        MROWS, NX, 4 * NX, 0, 0, 0, 0, 1.0f);

    // 7. out = LN(n + m)
    ln_kernel<<<MROWS, 256>>>(nbuf, tmp, ln2_g, ln2_b, out, nullptr);
}

// round 16
// speedup vs baseline: 1.5375x; 1.5375x over previous
#include <cuda_runtime.h>
#include <cuda_fp16.h>
#include <math.h>
#include <stdint.h>

// Problem constants
#define NX     768
#define NHEAD  12
#define DH     64
#define NCTX   2048
#define BATCH  4
#define MROWS  (BATCH * NCTX)        // 8192
#define EPS    1e-5f
#define NEGBIG -1000000000.0f

// ---------------- scratch (no allocations allowed) ----------------
__device__ float g_n   [MROWS * NX];
__device__ float g_tmp [MROWS * NX];
__device__ __half g_ahi[MROWS * NX];
__device__ __half g_hhi[MROWS * 4 * NX];   // also holds qkv hi (2304<=3072)
__device__ __half g_hlo[MROWS * 4 * NX];   // also holds qkv lo (Q,K only used)
#define WOFF_ATTN 0
#define WOFF_PROJ (3*NX*NX)
#define WOFF_FC   (WOFF_PROJ + NX*NX)
#define WOFF_FC2  (WOFF_FC + 4*NX*NX)
#define WTOTAL    (WOFF_FC2 + 4*NX*NX)
__device__ __half g_whi[WTOTAL];           // fp16 weights

// =====================================================================
// helpers
// =====================================================================
__device__ __forceinline__ uint32_t smem_u32(const void* p) {
    uint32_t a;
    asm("{ .reg .u64 t; cvta.to.shared.u64 t, %1; cvt.u32.u64 %0, t; }" : "=r"(a) : "l"(p));
    return a;
}
__device__ __forceinline__ void cp_async16(uint32_t s, const void* g) {
    asm volatile("cp.async.cg.shared.global [%0], [%1], 16;\n"
                 :: "r"(s), "l"(__cvta_generic_to_global(g)));
}
#define CP_COMMIT()   asm volatile("cp.async.commit_group;\n" ::: "memory")
#define CP_WAIT(n)    asm volatile("cp.async.wait_group %0;\n" :: "n"(n) : "memory")

__device__ __forceinline__ void ldsm_x4(uint32_t* r, uint32_t addr) {
    asm volatile("ldmatrix.sync.aligned.m8n8.x4.shared.b16 {%0,%1,%2,%3}, [%4];"
                 : "=r"(r[0]), "=r"(r[1]), "=r"(r[2]), "=r"(r[3]) : "r"(addr));
}
__device__ __forceinline__ void ldsm_x4_t(uint32_t* r, uint32_t addr) {
    asm volatile("ldmatrix.sync.aligned.m8n8.x4.trans.shared.b16 {%0,%1,%2,%3}, [%4];"
                 : "=r"(r[0]), "=r"(r[1]), "=r"(r[2]), "=r"(r[3]) : "r"(addr));
}
__device__ __forceinline__ void mma16816(float* d, const uint32_t* a, const uint32_t* b) {
    asm volatile(
        "mma.sync.aligned.m16n8k16.row.col.f32.f16.f16.f32 "
        "{%0,%1,%2,%3}, {%4,%5,%6,%7}, {%8,%9}, {%0,%1,%2,%3};"
        : "+f"(d[0]), "+f"(d[1]), "+f"(d[2]), "+f"(d[3])
        : "r"(a[0]), "r"(a[1]), "r"(a[2]), "r"(a[3]), "r"(b[0]), "r"(b[1]));
}
__device__ __forceinline__ uint32_t pack_h2(float a, float b) {
    __half2 t = __floats2half2_rn(a, b);
    return *reinterpret_cast<uint32_t*>(&t);
}

// =====================================================================
// Pure fp16 HMMA GEMM: C = Ahi @ Whi^T + bias
// Tile 128x128x64 (BK=64), 2 CTAs/SM, 2-stage cp.async (R12 proven).
// lo_cols: columns < lo_cols also emit the fp16 residual.
// =====================================================================
#define GST    72                          // smem row stride in halves (144B)
#define TILEB  (128 * GST * 2)             // 18432
#define STAGEB (2 * TILEB)                 // 36864 (A + B)
#define GEMM_DSMEM 73728                   // 2 stages

__global__ __launch_bounds__(256, 2) void gemm_tc_kernel(
    const __half* __restrict__ Ahi,
    const __half* __restrict__ Bhi,
    const float* __restrict__ bias,
    float* __restrict__ C, __half* __restrict__ Hhi, __half* __restrict__ Hlo,
    int M, int N, int K, int relu, int lo_cols)
{
    extern __shared__ __align__(16) char dsm[];
    const uint32_t sbase = smem_u32(dsm);

    const int tid  = threadIdx.x;
    const int wid  = tid >> 5;
    const int lane = tid & 31;
    const int wm   = wid >> 2;
    const int wn   = wid & 3;
    const int row0 = blockIdx.y * 128;
    const int col0 = blockIdx.x * 128;

    float acc[4][4][4];
#pragma unroll
    for (int mi = 0; mi < 4; mi++)
#pragma unroll
        for (int ni = 0; ni < 4; ni++)
#pragma unroll
            for (int j = 0; j < 4; j++) acc[mi][ni][j] = 0.0f;

    const int nchunks = K >> 6;

    auto load_stage = [&](int i) {
        const uint32_t st = sbase + (i & 1) * STAGEB;
        const int kt = i << 6;
#pragma unroll 8
        for (int u = tid; u < 2048; u += 256) {
            int t8 = u >> 10;                  // 0: A, 1: B
            int v = u & 1023;
            int r = v >> 3, c = v & 7;
            uint32_t off = (uint32_t)(t8 * TILEB + r * (GST * 2) + c * 16);
            const __half* src = t8 ? (Bhi + (size_t)(col0 + r) * K + kt + c * 8)
                                   : (Ahi + (size_t)(row0 + r) * K + kt + c * 8);
            cp_async16(st + off, src);
        }
        CP_COMMIT();
    };

    load_stage(0);
    if (nchunks > 1) load_stage(1);

    const int lr8 = lane & 7;
    const int lg  = lane >> 3;
    const int a_row = lr8 + (lg & 1) * 8;
    const int a_col = (lg >> 1) * 8;
    const int b_rowg = (lg >> 1) * 8 + lr8;
    const int b_colg = (lg & 1) * 8;

    for (int i = 0; i < nchunks; i++) {
        if (i + 1 < nchunks) CP_WAIT(1); else CP_WAIT(0);
        __syncthreads();

        const uint32_t st  = sbase + (i & 1) * STAGEB;
        const uint32_t sAh = st;
        const uint32_t sBh = st + TILEB;

#pragma unroll
        for (int ks = 0; ks < 4; ks++) {
            const int kc = ks * 16;
            uint32_t bhi[4][2];
#pragma unroll
            for (int p = 0; p < 2; p++) {
                int nrow = wn * 32 + p * 16 + b_rowg;
                uint32_t off = (uint32_t)(nrow * (GST * 2) + (kc + b_colg) * 2);
                uint32_t r4[4];
                ldsm_x4(r4, sBh + off);
                bhi[p*2][0] = r4[0]; bhi[p*2][1] = r4[1];
                bhi[p*2+1][0] = r4[2]; bhi[p*2+1][1] = r4[3];
            }
#pragma unroll
            for (int mi = 0; mi < 4; mi++) {
                int mrow = wm * 64 + mi * 16 + a_row;
                uint32_t off = (uint32_t)(mrow * (GST * 2) + (kc + a_col) * 2);
                uint32_t ah[4];
                ldsm_x4(ah, sAh + off);
#pragma unroll
                for (int ni = 0; ni < 4; ni++)
                    mma16816(acc[mi][ni], ah, bhi[ni]);
            }
        }
        __syncthreads();
        if (i + 2 < nchunks) load_stage(i + 2);
    }

    float* sof = (float*)dsm;
    const int qr = lane >> 2;
    const int qc2 = (lane & 3) * 2;
#pragma unroll
    for (int mi = 0; mi < 4; mi++) {
#pragma unroll
        for (int ni = 0; ni < 4; ni++) {
            int r = wm * 64 + mi * 16 + qr;
            int c = wn * 32 + ni * 8 + qc2;
            *(float2*)(sof + r * 132 + c)       = make_float2(acc[mi][ni][0], acc[mi][ni][1]);
            *(float2*)(sof + (r + 8) * 132 + c) = make_float2(acc[mi][ni][2], acc[mi][ni][3]);
        }
    }
    __syncthreads();

    for (int i = tid; i < 128 * 32; i += 256) {
        int r = i >> 5, cu = i & 31;
        float4 v = *(float4*)(sof + r * 132 + cu * 4);
        int gcol = col0 + cu * 4;
        float4 bb = *(const float4*)(bias + gcol);
        v.x += bb.x; v.y += bb.y; v.z += bb.z; v.w += bb.w;
        if (relu) {
            v.x = fmaxf(v.x, 0.0f); v.y = fmaxf(v.y, 0.0f);
            v.z = fmaxf(v.z, 0.0f); v.w = fmaxf(v.w, 0.0f);
        }
        size_t gi = (size_t)(row0 + r) * N + gcol;
        if (C) *(float4*)(C + gi) = v;
        if (Hhi) {
            __half h0 = __float2half_rn(v.x), h1 = __float2half_rn(v.y);
            __half h2 = __float2half_rn(v.z), h3 = __float2half_rn(v.w);
            __half2 p0; p0.x = h0; p0.y = h1;
            __half2 p1; p1.x = h2; p1.y = h3;
            *(__half2*)(Hhi + gi) = p0;
            *(__half2*)(Hhi + gi + 2) = p1;
            if (Hlo && gcol < lo_cols) {
                __half2 q0, q1;
                q0.x = __float2half_rn(v.x - __half2float(h0));
                q0.y = __float2half_rn(v.y - __half2float(h1));
                q1.x = __float2half_rn(v.z - __half2float(h2));
                q1.y = __float2half_rn(v.w - __half2float(h3));
                *(__half2*)(Hlo + gi) = q0;
                *(__half2*)(Hlo + gi + 2) = q1;
            }
        }
    }
}

// =====================================================================
// HMMA flash attention: QK 3-term, PV 2-term, __expf softmax.
// Double-buffered K/V stages; heavy tiles scheduled first. (R12 exact)
// =====================================================================
#define AST    72
#define A_Q_BYTES  (128 * AST * 2)
#define A_KV_BYTES (64 * AST * 2)
#define KVSTAGE    (3 * A_KV_BYTES)
#define SQH 0
#define SQL (A_Q_BYTES)
#define KVBASE (2 * A_Q_BYTES)
#define ATTN_DSMEM (2 * A_Q_BYTES + 2 * KVSTAGE)   // 92160

__global__ __launch_bounds__(256) void attn_mma_kernel(
    const __half* __restrict__ qh_, const __half* __restrict__ ql_,
    __half* __restrict__ ohi_)
{
    extern __shared__ __align__(16) char dsm[];
    const uint32_t sb = smem_u32(dsm);

    const int tid  = threadIdx.x;
    const int wid  = tid >> 5;
    const int lane = tid & 31;
    const int it = (int)gridDim.x - 1 - (int)blockIdx.x;
    const int h  = blockIdx.y;
    const int b  = blockIdx.z;
    const int row0  = it * 128;
    const int grow0 = b * NCTX + row0;

    for (int u = tid; u < 1024; u += 256) {
        int r = u >> 3, c = u & 7;
        uint32_t off = (uint32_t)(r * (AST * 2) + c * 16);
        size_t gi = (size_t)(grow0 + r) * (3 * NX) + h * DH + c * 8;
        cp_async16(sb + SQH + off, qh_ + gi);
        cp_async16(sb + SQL + off, ql_ + gi);
    }
    CP_COMMIT();

    const int wr  = wid * 16;
    const int lr  = lane >> 2;
    const int qc  = lane & 3;
    const int lr8 = lane & 7;
    const int lg  = lane >> 3;
    const int a_row = lr8 + (lg & 1) * 8;
    const int a_col = (lg >> 1) * 8;
    const int b_rowg = (lg >> 1) * 8 + lr8;
    const int b_colg = (lg & 1) * 8;
    const int v_row = (lg & 1) * 8 + lr8;
    const int v_col = (lg >> 1) * 8;

    const int jmax = 2 * it + 1;

    auto load_kv = [&](int jt) {
        const uint32_t st = sb + KVBASE + (jt & 1) * KVSTAGE;
        for (int u = tid; u < 512; u += 256) {
            int r = u >> 3, c = u & 7;
            uint32_t off = (uint32_t)(r * (AST * 2) + c * 16);
            size_t gk = (size_t)(b * NCTX + jt * 64 + r) * (3 * NX) + NX + h * DH + c * 8;
            cp_async16(st + off,                   qh_ + gk);
            cp_async16(st + A_KV_BYTES + off,      ql_ + gk);
            cp_async16(st + 2 * A_KV_BYTES + off,  qh_ + gk + NX);
        }
        CP_COMMIT();
    };

    load_kv(0);
    CP_WAIT(0);
    __syncthreads();

    uint32_t qh[4][4], ql[4][4];
#pragma unroll
    for (int kk = 0; kk < 4; kk++) {
        uint32_t off = (uint32_t)((wr + a_row) * (AST * 2) + (kk * 16 + a_col) * 2);
        ldsm_x4(qh[kk], sb + SQH + off);
        ldsm_x4(ql[kk], sb + SQL + off);
    }

    float m0 = -INFINITY, m1 = -INFINITY, l0 = 0.0f, l1 = 0.0f;
    float o[8][4];
#pragma unroll
    for (int ni = 0; ni < 8; ni++)
#pragma unroll
        for (int e = 0; e < 4; e++) o[ni][e] = 0.0f;

    for (int jt = 0; jt <= jmax; jt++) {
        if (jt + 1 <= jmax) { load_kv(jt + 1); CP_WAIT(1); }
        else                { CP_WAIT(0); }
        __syncthreads();

        const uint32_t st = sb + KVBASE + (jt & 1) * KVSTAGE;
        const uint32_t sKH = st;
        const uint32_t sKL = st + A_KV_BYTES;
        const uint32_t sVH = st + 2 * A_KV_BYTES;

        const int col0 = jt * 64;
        const bool fullmask = col0 > row0 + wr + 15;
        if (!fullmask) {
            float s[8][4];
#pragma unroll
            for (int ni = 0; ni < 8; ni++)
#pragma unroll
                for (int e = 0; e < 4; e++) s[ni][e] = 0.0f;

#pragma unroll
            for (int kk = 0; kk < 4; kk++) {
                uint32_t bh[8][2], bl[8][2];
#pragma unroll
                for (int p = 0; p < 4; p++) {
                    uint32_t off = (uint32_t)((p * 16 + b_rowg) * (AST * 2) + (kk * 16 + b_colg) * 2);
                    uint32_t r4[4];
                    ldsm_x4(r4, sKH + off);
                    bh[p*2][0] = r4[0]; bh[p*2][1] = r4[1];
                    bh[p*2+1][0] = r4[2]; bh[p*2+1][1] = r4[3];
                    ldsm_x4(r4, sKL + off);
                    bl[p*2][0] = r4[0]; bl[p*2][1] = r4[1];
                    bl[p*2+1][0] = r4[2]; bl[p*2+1][1] = r4[3];
                }
#pragma unroll
                for (int ni = 0; ni < 8; ni++) {
                    mma16816(s[ni], qh[kk], bh[ni]);
                    mma16816(s[ni], ql[kk], bh[ni]);
                    mma16816(s[ni], qh[kk], bl[ni]);
                }
            }

            if (col0 + 63 > row0 + wr) {
                const int gr0 = row0 + wr + lr;
#pragma unroll
                for (int ni = 0; ni < 8; ni++) {
                    int gc = col0 + ni * 8 + qc * 2;
                    if (gc > gr0)         s[ni][0] = NEGBIG;
                    if (gc + 1 > gr0)     s[ni][1] = NEGBIG;
                    if (gc > gr0 + 8)     s[ni][2] = NEGBIG;
                    if (gc + 1 > gr0 + 8) s[ni][3] = NEGBIG;
                }
            }

            float mt0 = s[0][0], mt1 = s[0][2];
#pragma unroll
            for (int ni = 0; ni < 8; ni++) {
                mt0 = fmaxf(mt0, fmaxf(s[ni][0], s[ni][1]));
                mt1 = fmaxf(mt1, fmaxf(s[ni][2], s[ni][3]));
            }
            mt0 = fmaxf(mt0, __shfl_xor_sync(0xffffffffu, mt0, 1));
            mt0 = fmaxf(mt0, __shfl_xor_sync(0xffffffffu, mt0, 2));
            mt1 = fmaxf(mt1, __shfl_xor_sync(0xffffffffu, mt1, 1));
            mt1 = fmaxf(mt1, __shfl_xor_sync(0xffffffffu, mt1, 2));
            float mn0 = fmaxf(m0, mt0), mn1 = fmaxf(m1, mt1);
            float al0 = __expf(m0 - mn0), al1 = __expf(m1 - mn1);
            m0 = mn0; m1 = mn1;

            float sum0 = 0.0f, sum1 = 0.0f;
#pragma unroll
            for (int ni = 0; ni < 8; ni++) {
                s[ni][0] = __expf(s[ni][0] - mn0);
                s[ni][1] = __expf(s[ni][1] - mn0);
                s[ni][2] = __expf(s[ni][2] - mn1);
                s[ni][3] = __expf(s[ni][3] - mn1);
                sum0 += s[ni][0] + s[ni][1];
                sum1 += s[ni][2] + s[ni][3];
            }
            sum0 += __shfl_xor_sync(0xffffffffu, sum0, 1);
            sum0 += __shfl_xor_sync(0xffffffffu, sum0, 2);
            sum1 += __shfl_xor_sync(0xffffffffu, sum1, 1);
            sum1 += __shfl_xor_sync(0xffffffffu, sum1, 2);
            l0 = l0 * al0 + sum0;
            l1 = l1 * al1 + sum1;

#pragma unroll
            for (int ni = 0; ni < 8; ni++) {
                o[ni][0] *= al0; o[ni][1] *= al0;
                o[ni][2] *= al1; o[ni][3] *= al1;
            }

#pragma unroll
            for (int kk = 0; kk < 4; kk++) {
                uint32_t pa_h[4], pa_l[4];
                {
                    float p00 = s[2*kk][0],   p01 = s[2*kk][1];
                    float p10 = s[2*kk][2],   p11 = s[2*kk][3];
                    float p20 = s[2*kk+1][0], p21 = s[2*kk+1][1];
                    float p30 = s[2*kk+1][2], p31 = s[2*kk+1][3];
                    pa_h[0] = pack_h2(p00, p01);
                    pa_h[1] = pack_h2(p10, p11);
                    pa_h[2] = pack_h2(p20, p21);
                    pa_h[3] = pack_h2(p30, p31);
                    __half2 t;
                    t = *(__half2*)&pa_h[0];
                    pa_l[0] = pack_h2(p00 - __half2float(t.x), p01 - __half2float(t.y));
                    t = *(__half2*)&pa_h[1];
                    pa_l[1] = pack_h2(p10 - __half2float(t.x), p11 - __half2float(t.y));
                    t = *(__half2*)&pa_h[2];
                    pa_l[2] = pack_h2(p20 - __half2float(t.x), p21 - __half2float(t.y));
                    t = *(__half2*)&pa_h[3];
                    pa_l[3] = pack_h2(p30 - __half2float(t.x), p31 - __half2float(t.y));
                }
                uint32_t vh[8][2];
#pragma unroll
                for (int p = 0; p < 4; p++) {
                    uint32_t off = (uint32_t)((kk * 16 + v_row) * (AST * 2) + (p * 16 + v_col) * 2);
                    uint32_t r4[4];
                    ldsm_x4_t(r4, sVH + off);
                    vh[p*2][0] = r4[0]; vh[p*2][1] = r4[1];
                    vh[p*2+1][0] = r4[2]; vh[p*2+1][1] = r4[3];
                }
#pragma unroll
                for (int ni = 0; ni < 8; ni++) {
                    mma16816(o[ni], pa_h, vh[ni]);
                    mma16816(o[ni], pa_l, vh[ni]);
                }
            }
        }
        __syncthreads();
    }

    const float inv0 = 1.0f / l0, inv1 = 1.0f / l1;
    const int gr = grow0 + wr + lr;
    const int gcb = h * DH + qc * 2;
#pragma unroll
    for (int ni = 0; ni < 8; ni++) {
        float v0 = o[ni][0] * inv0, v1 = o[ni][1] * inv0;
        float v2 = o[ni][2] * inv1, v3 = o[ni][3] * inv1;
        size_t i0 = (size_t)gr * NX + gcb + ni * 8;
        size_t i1 = (size_t)(gr + 8) * NX + gcb + ni * 8;
        *(uint32_t*)(ohi_ + i0) = pack_h2(v0, v1);
        *(uint32_t*)(ohi_ + i1) = pack_h2(v2, v3);
    }
}

// =====================================================================
// weight transpose (fp16): Wt[n][k] = fp16(W[k][n])
// =====================================================================
__global__ __launch_bounds__(256) void tsplit_kernel(
    const float* __restrict__ W, __half* __restrict__ hi, int K, int N)
{
    __shared__ float t[32][33];
    const int n0 = blockIdx.x * 32, k0 = blockIdx.y * 32;
    const int tx = threadIdx.x & 31, ty = threadIdx.x >> 5;
#pragma unroll
    for (int i = 0; i < 32; i += 8)
        t[ty + i][tx] = W[(size_t)(k0 + ty + i) * N + n0 + tx];
    __syncthreads();
#pragma unroll
    for (int i = 0; i < 32; i += 8) {
        float v = t[tx][ty + i];
        hi[(size_t)(n0 + ty + i) * K + k0 + tx] = __float2half_rn(v);
    }
}

// fp16 convert (hi only)
__global__ __launch_bounds__(256) void split_kernel(
    const float* __restrict__ in, __half* __restrict__ hi, int n4)
{
    int i = blockIdx.x * blockDim.x + threadIdx.x;
    if (i >= n4) return;
    float4 v = *(const float4*)(in + i * 4);
    __half2 p0 = __floats2half2_rn(v.x, v.y);
    __half2 p1 = __floats2half2_rn(v.z, v.w);
    *(__half2*)(hi + i * 4) = p0;
    *(__half2*)(hi + i * 4 + 2) = p1;
}

// =====================================================================
// LayerNorm (additive, faithful to source bug) + optional fp16 out (hi only)
// =====================================================================
__global__ __launch_bounds__(256) void ln_kernel(
    const float* __restrict__ in1, const float* __restrict__ in2,
    const float* __restrict__ g, const float* __restrict__ bb,
    float* __restrict__ out, __half* __restrict__ ohi)
{
    __shared__ float buf[NX];
    __shared__ float wsum[8], wsum2[8];

    const int row = blockIdx.x;
    const int tid = threadIdx.x;
    const int lane = tid & 31;
    const int wrp = tid >> 5;
    const size_t base = (size_t)row * NX;

    float s = 0.0f, s2 = 0.0f;
#pragma unroll
    for (int k = 0; k < 3; k++) {
        int i = tid + k * 256;
        float v = in1[base + i] + in2[base + i];
        buf[i] = v;
        s += v; s2 += v * v;
    }
#pragma unroll
    for (int off = 16; off > 0; off >>= 1) {
        s  += __shfl_xor_sync(0xffffffffu, s,  off);
        s2 += __shfl_xor_sync(0xffffffffu, s2, off);
    }
    if (lane == 0) { wsum[wrp] = s; wsum2[wrp] = s2; }
    __syncthreads();
    if (wrp == 0) {
        float a = (lane < 8) ? wsum[lane] : 0.0f;
        float a2 = (lane < 8) ? wsum2[lane] : 0.0f;
#pragma unroll
        for (int off = 4; off > 0; off >>= 1) {
            a  += __shfl_xor_sync(0xffffffffu, a,  off);
            a2 += __shfl_xor_sync(0xffffffffu, a2, off);
        }
        if (lane == 0) { wsum[0] = a; wsum2[0] = a2; }
    }
    __syncthreads();
    const float u = wsum[0] * (1.0f / NX);
    const float var = wsum2[0] * (1.0f / NX) - u * u;
    const float rstd = rsqrtf(var + EPS);
#pragma unroll
    for (int k = 0; k < 3; k++) {
        int i = tid + k * 256;
        float v = g[i] + (buf[i] - u) * rstd + bb[i];
        out[base + i] = v;
        if (ohi) ohi[base + i] = __float2half_rn(v);
    }
}

// =====================================================================
extern "C" void kernel_launch(void* const* d_in, const int* in_sizes, int n_in,
                              void* d_out, int out_size)
{
    const float* x      = (const float*)d_in[0];
    const float* w_attn = (const float*)d_in[1];
    const float* b_attn = (const float*)d_in[2];
    const float* w_proj = (const float*)d_in[3];
    const float* b_proj = (const float*)d_in[4];
    const float* ln1_g  = (const float*)d_in[5];
    const float* ln1_b  = (const float*)d_in[6];
    const float* w_fc   = (const float*)d_in[7];
    const float* b_fc   = (const float*)d_in[8];
    const float* w_fc2  = (const float*)d_in[9];
    const float* b_fc2  = (const float*)d_in[10];
    const float* ln2_g  = (const float*)d_in[11];
    const float* ln2_b  = (const float*)d_in[12];
    float* out = (float*)d_out;

    float *nbuf, *tmp;
    __half *ahi, *hhi, *hlo, *whi;
    cudaGetSymbolAddress((void**)&nbuf, g_n);
    cudaGetSymbolAddress((void**)&tmp,  g_tmp);
    cudaGetSymbolAddress((void**)&ahi,  g_ahi);
    cudaGetSymbolAddress((void**)&hhi,  g_hhi);
    cudaGetSymbolAddress((void**)&hlo,  g_hlo);
    cudaGetSymbolAddress((void**)&whi,  g_whi);

    static int smem_set = 0;
    if (!smem_set) {
        cudaFuncSetAttribute(gemm_tc_kernel,
                             cudaFuncAttributeMaxDynamicSharedMemorySize, GEMM_DSMEM);
        cudaFuncSetAttribute(attn_mma_kernel,
                             cudaFuncAttributeMaxDynamicSharedMemorySize, ATTN_DSMEM);
        smem_set = 1;
    }

    // --- weight prep (fp16) ---
    tsplit_kernel<<<dim3(3 * NX / 32, NX / 32), 256>>>(w_attn, whi + WOFF_ATTN, NX, 3 * NX);
    tsplit_kernel<<<dim3(NX / 32, NX / 32),     256>>>(w_proj, whi + WOFF_PROJ, NX, NX);
    tsplit_kernel<<<dim3(4 * NX / 32, NX / 32), 256>>>(w_fc,   whi + WOFF_FC,   NX, 4 * NX);
    tsplit_kernel<<<dim3(NX / 32, 4 * NX / 32), 256>>>(w_fc2,  whi + WOFF_FC2,  4 * NX, NX);

    // --- x -> fp16 ---
    split_kernel<<<(MROWS * NX / 4 + 255) / 256, 256>>>(x, ahi, MROWS * NX / 4);

    // 1. qkv = x @ w_attn + b_attn  -> fp16 hi (all) + lo (Q,K cols only)
    gemm_tc_kernel<<<dim3(3 * NX / 128, MROWS / 128), 256, GEMM_DSMEM>>>(
        ahi, whi + WOFF_ATTN, b_attn, nullptr, hhi, hlo,
        MROWS, 3 * NX, NX, 0, 2 * NX);

    // 2. attention (QK 3-term, PV 2-term)
    attn_mma_kernel<<<dim3(NCTX / 128, NHEAD, BATCH), 256, ATTN_DSMEM>>>(
        hhi, hlo, ahi);

    // 3. proj = attn @ w_proj + b_proj -> tmp fp32
    gemm_tc_kernel<<<dim3(NX / 128, MROWS / 128), 256, GEMM_DSMEM>>>(
        ahi, whi + WOFF_PROJ, b_proj, tmp, nullptr, nullptr,
        MROWS, NX, NX, 0, 0);

    // 4. n = LN(x + proj) -> nbuf fp32 + ahi fp16
    ln_kernel<<<MROWS, 256>>>(x, tmp, ln1_g, ln1_b, nbuf, ahi);

    // 5. h = relu(n @ w_fc + b_fc) -> hhi fp16 only
    gemm_tc_kernel<<<dim3(4 * NX / 128, MROWS / 128), 256, GEMM_DSMEM>>>(
        ahi, whi + WOFF_FC, b_fc, nullptr, hhi, nullptr,
        MROWS, 4 * NX, NX, 1, 0);

    // 6. m = h @ w_fc2 + b_fc2 -> tmp
    gemm_tc_kernel<<<dim3(NX / 128, MROWS / 128), 256, GEMM_DSMEM>>>(
        hhi, whi + WOFF_FC2, b_fc2, tmp, nullptr, nullptr,
        MROWS, NX, 4 * NX, 0, 0);

    // 7. out = LN(n + m)
    ln_kernel<<<MROWS, 256>>>(nbuf, tmp, ln2_g, ln2_b, out, nullptr);
}

// round 17
// speedup vs baseline: 1.5835x; 1.0299x over previous
#include <cuda_runtime.h>
#include <cuda_fp16.h>
#include <math.h>
#include <stdint.h>

// Problem constants
#define NX     768
#define NHEAD  12
#define DH     64
#define NCTX   2048
#define BATCH  4
#define MROWS  (BATCH * NCTX)        // 8192
#define EPS    1e-5f
#define NEGBIG -1000000000.0f

// ---------------- scratch (no allocations allowed) ----------------
__device__ float g_n   [MROWS * NX];
__device__ float g_tmp [MROWS * NX];
__device__ __half g_ahi[MROWS * NX];
__device__ __half g_hhi[MROWS * 4 * NX];   // also holds qkv hi (2304<=3072)
__device__ __half g_hlo[MROWS * 4 * NX];   // also holds qkv lo (Q,K only used)
#define WOFF_ATTN 0
#define WOFF_PROJ (3*NX*NX)
#define WOFF_FC   (WOFF_PROJ + NX*NX)
#define WOFF_FC2  (WOFF_FC + 4*NX*NX)
#define WTOTAL    (WOFF_FC2 + 4*NX*NX)
__device__ __half g_whi[WTOTAL];           // fp16 weights

// =====================================================================
// helpers
// =====================================================================
__device__ __forceinline__ uint32_t smem_u32(const void* p) {
    uint32_t a;
    asm("{ .reg .u64 t; cvta.to.shared.u64 t, %1; cvt.u32.u64 %0, t; }" : "=r"(a) : "l"(p));
    return a;
}
__device__ __forceinline__ void cp_async16(uint32_t s, const void* g) {
    asm volatile("cp.async.cg.shared.global [%0], [%1], 16;\n"
                 :: "r"(s), "l"(__cvta_generic_to_global(g)));
}
#define CP_COMMIT()   asm volatile("cp.async.commit_group;\n" ::: "memory")
#define CP_WAIT(n)    asm volatile("cp.async.wait_group %0;\n" :: "n"(n) : "memory")

__device__ __forceinline__ void ldsm_x4(uint32_t* r, uint32_t addr) {
    asm volatile("ldmatrix.sync.aligned.m8n8.x4.shared.b16 {%0,%1,%2,%3}, [%4];"
                 : "=r"(r[0]), "=r"(r[1]), "=r"(r[2]), "=r"(r[3]) : "r"(addr));
}
__device__ __forceinline__ void ldsm_x4_t(uint32_t* r, uint32_t addr) {
    asm volatile("ldmatrix.sync.aligned.m8n8.x4.trans.shared.b16 {%0,%1,%2,%3}, [%4];"
                 : "=r"(r[0]), "=r"(r[1]), "=r"(r[2]), "=r"(r[3]) : "r"(addr));
}
__device__ __forceinline__ void mma16816(float* d, const uint32_t* a, const uint32_t* b) {
    asm volatile(
        "mma.sync.aligned.m16n8k16.row.col.f32.f16.f16.f32 "
        "{%0,%1,%2,%3}, {%4,%5,%6,%7}, {%8,%9}, {%0,%1,%2,%3};"
        : "+f"(d[0]), "+f"(d[1]), "+f"(d[2]), "+f"(d[3])
        : "r"(a[0]), "r"(a[1]), "r"(a[2]), "r"(a[3]), "r"(b[0]), "r"(b[1]));
}
__device__ __forceinline__ uint32_t pack_h2(float a, float b) {
    __half2 t = __floats2half2_rn(a, b);
    return *reinterpret_cast<uint32_t*>(&t);
}

// =====================================================================
// Pure fp16 HMMA GEMM: C = Ahi @ Whi^T + bias
// Tile 128x128x64 (BK=64), 2 CTAs/SM, 2-stage cp.async (R12 proven).
// lo_cols: columns < lo_cols also emit the fp16 residual.
// =====================================================================
#define GST    72                          // smem row stride in halves (144B)
#define TILEB  (128 * GST * 2)             // 18432
#define STAGEB (2 * TILEB)                 // 36864 (A + B)
#define GEMM_DSMEM 73728                   // 2 stages

__global__ __launch_bounds__(256, 2) void gemm_tc_kernel(
    const __half* __restrict__ Ahi,
    const __half* __restrict__ Bhi,
    const float* __restrict__ bias,
    float* __restrict__ C, __half* __restrict__ Hhi, __half* __restrict__ Hlo,
    int M, int N, int K, int relu, int lo_cols)
{
    extern __shared__ __align__(16) char dsm[];
    const uint32_t sbase = smem_u32(dsm);

    const int tid  = threadIdx.x;
    const int wid  = tid >> 5;
    const int lane = tid & 31;
    const int wm   = wid >> 2;
    const int wn   = wid & 3;
    const int row0 = blockIdx.y * 128;
    const int col0 = blockIdx.x * 128;

    float acc[4][4][4];
#pragma unroll
    for (int mi = 0; mi < 4; mi++)
#pragma unroll
        for (int ni = 0; ni < 4; ni++)
#pragma unroll
            for (int j = 0; j < 4; j++) acc[mi][ni][j] = 0.0f;

    const int nchunks = K >> 6;

    auto load_stage = [&](int i) {
        const uint32_t st = sbase + (i & 1) * STAGEB;
        const int kt = i << 6;
#pragma unroll 8
        for (int u = tid; u < 2048; u += 256) {
            int t8 = u >> 10;                  // 0: A, 1: B
            int v = u & 1023;
            int r = v >> 3, c = v & 7;
            uint32_t off = (uint32_t)(t8 * TILEB + r * (GST * 2) + c * 16);
            const __half* src = t8 ? (Bhi + (size_t)(col0 + r) * K + kt + c * 8)
                                   : (Ahi + (size_t)(row0 + r) * K + kt + c * 8);
            cp_async16(st + off, src);
        }
        CP_COMMIT();
    };

    load_stage(0);
    if (nchunks > 1) load_stage(1);

    const int lr8 = lane & 7;
    const int lg  = lane >> 3;
    const int a_row = lr8 + (lg & 1) * 8;
    const int a_col = (lg >> 1) * 8;
    const int b_rowg = (lg >> 1) * 8 + lr8;
    const int b_colg = (lg & 1) * 8;

    for (int i = 0; i < nchunks; i++) {
        if (i + 1 < nchunks) CP_WAIT(1); else CP_WAIT(0);
        __syncthreads();

        const uint32_t st  = sbase + (i & 1) * STAGEB;
        const uint32_t sAh = st;
        const uint32_t sBh = st + TILEB;

#pragma unroll
        for (int ks = 0; ks < 4; ks++) {
            const int kc = ks * 16;
            uint32_t bhi[4][2];
#pragma unroll
            for (int p = 0; p < 2; p++) {
                int nrow = wn * 32 + p * 16 + b_rowg;
                uint32_t off = (uint32_t)(nrow * (GST * 2) + (kc + b_colg) * 2);
                uint32_t r4[4];
                ldsm_x4(r4, sBh + off);
                bhi[p*2][0] = r4[0]; bhi[p*2][1] = r4[1];
                bhi[p*2+1][0] = r4[2]; bhi[p*2+1][1] = r4[3];
            }
#pragma unroll
            for (int mi = 0; mi < 4; mi++) {
                int mrow = wm * 64 + mi * 16 + a_row;
                uint32_t off = (uint32_t)(mrow * (GST * 2) + (kc + a_col) * 2);
                uint32_t ah[4];
                ldsm_x4(ah, sAh + off);
#pragma unroll
                for (int ni = 0; ni < 4; ni++)
                    mma16816(acc[mi][ni], ah, bhi[ni]);
            }
        }
        __syncthreads();
        if (i + 2 < nchunks) load_stage(i + 2);
    }

    float* sof = (float*)dsm;
    const int qr = lane >> 2;
    const int qc2 = (lane & 3) * 2;
#pragma unroll
    for (int mi = 0; mi < 4; mi++) {
#pragma unroll
        for (int ni = 0; ni < 4; ni++) {
            int r = wm * 64 + mi * 16 + qr;
            int c = wn * 32 + ni * 8 + qc2;
            *(float2*)(sof + r * 132 + c)       = make_float2(acc[mi][ni][0], acc[mi][ni][1]);
            *(float2*)(sof + (r + 8) * 132 + c) = make_float2(acc[mi][ni][2], acc[mi][ni][3]);
        }
    }
    __syncthreads();

    for (int i = tid; i < 128 * 32; i += 256) {
        int r = i >> 5, cu = i & 31;
        float4 v = *(float4*)(sof + r * 132 + cu * 4);
        int gcol = col0 + cu * 4;
        float4 bb = *(const float4*)(bias + gcol);
        v.x += bb.x; v.y += bb.y; v.z += bb.z; v.w += bb.w;
        if (relu) {
            v.x = fmaxf(v.x, 0.0f); v.y = fmaxf(v.y, 0.0f);
            v.z = fmaxf(v.z, 0.0f); v.w = fmaxf(v.w, 0.0f);
        }
        size_t gi = (size_t)(row0 + r) * N + gcol;
        if (C) *(float4*)(C + gi) = v;
        if (Hhi) {
            __half h0 = __float2half_rn(v.x), h1 = __float2half_rn(v.y);
            __half h2 = __float2half_rn(v.z), h3 = __float2half_rn(v.w);
            __half2 p0; p0.x = h0; p0.y = h1;
            __half2 p1; p1.x = h2; p1.y = h3;
            *(__half2*)(Hhi + gi) = p0;
            *(__half2*)(Hhi + gi + 2) = p1;
            if (Hlo && gcol < lo_cols) {
                __half2 q0, q1;
                q0.x = __float2half_rn(v.x - __half2float(h0));
                q0.y = __float2half_rn(v.y - __half2float(h1));
                q1.x = __float2half_rn(v.z - __half2float(h2));
                q1.y = __float2half_rn(v.w - __half2float(h3));
                *(__half2*)(Hlo + gi) = q0;
                *(__half2*)(Hlo + gi + 2) = q1;
            }
        }
    }
}

// =====================================================================
// HMMA flash attention: QK 3-term, PV 2-term, __expf softmax.
// Double-buffered K/V; heavy tiles first. NOW 2 CTAs/SM (reg cap 124).
// =====================================================================
#define AST    72
#define A_Q_BYTES  (128 * AST * 2)
#define A_KV_BYTES (64 * AST * 2)
#define KVSTAGE    (3 * A_KV_BYTES)
#define SQH 0
#define SQL (A_Q_BYTES)
#define KVBASE (2 * A_Q_BYTES)
#define ATTN_DSMEM (2 * A_Q_BYTES + 2 * KVSTAGE)   // 92160

__global__ __launch_bounds__(256, 2) void attn_mma_kernel(
    const __half* __restrict__ qh_, const __half* __restrict__ ql_,
    __half* __restrict__ ohi_)
{
    extern __shared__ __align__(16) char dsm[];
    const uint32_t sb = smem_u32(dsm);

    const int tid  = threadIdx.x;
    const int wid  = tid >> 5;
    const int lane = tid & 31;
    const int it = (int)gridDim.x - 1 - (int)blockIdx.x;
    const int h  = blockIdx.y;
    const int b  = blockIdx.z;
    const int row0  = it * 128;
    const int grow0 = b * NCTX + row0;

    for (int u = tid; u < 1024; u += 256) {
        int r = u >> 3, c = u & 7;
        uint32_t off = (uint32_t)(r * (AST * 2) + c * 16);
        size_t gi = (size_t)(grow0 + r) * (3 * NX) + h * DH + c * 8;
        cp_async16(sb + SQH + off, qh_ + gi);
        cp_async16(sb + SQL + off, ql_ + gi);
    }
    CP_COMMIT();

    const int wr  = wid * 16;
    const int lr  = lane >> 2;
    const int qc  = lane & 3;
    const int lr8 = lane & 7;
    const int lg  = lane >> 3;
    const int a_row = lr8 + (lg & 1) * 8;
    const int a_col = (lg >> 1) * 8;
    const int b_rowg = (lg >> 1) * 8 + lr8;
    const int b_colg = (lg & 1) * 8;
    const int v_row = (lg & 1) * 8 + lr8;
    const int v_col = (lg >> 1) * 8;

    const int jmax = 2 * it + 1;

    auto load_kv = [&](int jt) {
        const uint32_t st = sb + KVBASE + (jt & 1) * KVSTAGE;
        for (int u = tid; u < 512; u += 256) {
            int r = u >> 3, c = u & 7;
            uint32_t off = (uint32_t)(r * (AST * 2) + c * 16);
            size_t gk = (size_t)(b * NCTX + jt * 64 + r) * (3 * NX) + NX + h * DH + c * 8;
            cp_async16(st + off,                   qh_ + gk);
            cp_async16(st + A_KV_BYTES + off,      ql_ + gk);
            cp_async16(st + 2 * A_KV_BYTES + off,  qh_ + gk + NX);
        }
        CP_COMMIT();
    };

    load_kv(0);
    CP_WAIT(0);
    __syncthreads();

    uint32_t qh[4][4], ql[4][4];
#pragma unroll
    for (int kk = 0; kk < 4; kk++) {
        uint32_t off = (uint32_t)((wr + a_row) * (AST * 2) + (kk * 16 + a_col) * 2);
        ldsm_x4(qh[kk], sb + SQH + off);
        ldsm_x4(ql[kk], sb + SQL + off);
    }

    float m0 = -INFINITY, m1 = -INFINITY, l0 = 0.0f, l1 = 0.0f;
    float o[8][4];
#pragma unroll
    for (int ni = 0; ni < 8; ni++)
#pragma unroll
        for (int e = 0; e < 4; e++) o[ni][e] = 0.0f;

    for (int jt = 0; jt <= jmax; jt++) {
        if (jt + 1 <= jmax) { load_kv(jt + 1); CP_WAIT(1); }
        else                { CP_WAIT(0); }
        __syncthreads();

        const uint32_t st = sb + KVBASE + (jt & 1) * KVSTAGE;
        const uint32_t sKH = st;
        const uint32_t sKL = st + A_KV_BYTES;
        const uint32_t sVH = st + 2 * A_KV_BYTES;

        const int col0 = jt * 64;
        const bool fullmask = col0 > row0 + wr + 15;
        if (!fullmask) {
            float s[8][4];
#pragma unroll
            for (int ni = 0; ni < 8; ni++)
#pragma unroll
                for (int e = 0; e < 4; e++) s[ni][e] = 0.0f;

#pragma unroll
            for (int kk = 0; kk < 4; kk++) {
                uint32_t bh[8][2], bl[8][2];
#pragma unroll
                for (int p = 0; p < 4; p++) {
                    uint32_t off = (uint32_t)((p * 16 + b_rowg) * (AST * 2) + (kk * 16 + b_colg) * 2);
                    uint32_t r4[4];
                    ldsm_x4(r4, sKH + off);
                    bh[p*2][0] = r4[0]; bh[p*2][1] = r4[1];
                    bh[p*2+1][0] = r4[2]; bh[p*2+1][1] = r4[3];
                    ldsm_x4(r4, sKL + off);
                    bl[p*2][0] = r4[0]; bl[p*2][1] = r4[1];
                    bl[p*2+1][0] = r4[2]; bl[p*2+1][1] = r4[3];
                }
#pragma unroll
                for (int ni = 0; ni < 8; ni++) {
                    mma16816(s[ni], qh[kk], bh[ni]);
                    mma16816(s[ni], ql[kk], bh[ni]);
                    mma16816(s[ni], qh[kk], bl[ni]);
                }
            }

            if (col0 + 63 > row0 + wr) {
                const int gr0 = row0 + wr + lr;
#pragma unroll
                for (int ni = 0; ni < 8; ni++) {
                    int gc = col0 + ni * 8 + qc * 2;
                    if (gc > gr0)         s[ni][0] = NEGBIG;
                    if (gc + 1 > gr0)     s[ni][1] = NEGBIG;
                    if (gc > gr0 + 8)     s[ni][2] = NEGBIG;
                    if (gc + 1 > gr0 + 8) s[ni][3] = NEGBIG;
                }
            }

            float mt0 = s[0][0], mt1 = s[0][2];
#pragma unroll
            for (int ni = 0; ni < 8; ni++) {
                mt0 = fmaxf(mt0, fmaxf(s[ni][0], s[ni][1]));
                mt1 = fmaxf(mt1, fmaxf(s[ni][2], s[ni][3]));
            }
            mt0 = fmaxf(mt0, __shfl_xor_sync(0xffffffffu, mt0, 1));
            mt0 = fmaxf(mt0, __shfl_xor_sync(0xffffffffu, mt0, 2));
            mt1 = fmaxf(mt1, __shfl_xor_sync(0xffffffffu, mt1, 1));
            mt1 = fmaxf(mt1, __shfl_xor_sync(0xffffffffu, mt1, 2));
            float mn0 = fmaxf(m0, mt0), mn1 = fmaxf(m1, mt1);
            float al0 = __expf(m0 - mn0), al1 = __expf(m1 - mn1);
            m0 = mn0; m1 = mn1;

            float sum0 = 0.0f, sum1 = 0.0f;
#pragma unroll
            for (int ni = 0; ni < 8; ni++) {
                s[ni][0] = __expf(s[ni][0] - mn0);
                s[ni][1] = __expf(s[ni][1] - mn0);
                s[ni][2] = __expf(s[ni][2] - mn1);
                s[ni][3] = __expf(s[ni][3] - mn1);
                sum0 += s[ni][0] + s[ni][1];
                sum1 += s[ni][2] + s[ni][3];
            }
            sum0 += __shfl_xor_sync(0xffffffffu, sum0, 1);
            sum0 += __shfl_xor_sync(0xffffffffu, sum0, 2);
            sum1 += __shfl_xor_sync(0xffffffffu, sum1, 1);
            sum1 += __shfl_xor_sync(0xffffffffu, sum1, 2);
            l0 = l0 * al0 + sum0;
            l1 = l1 * al1 + sum1;

#pragma unroll
            for (int ni = 0; ni < 8; ni++) {
                o[ni][0] *= al0; o[ni][1] *= al0;
                o[ni][2] *= al1; o[ni][3] *= al1;
            }

#pragma unroll
            for (int kk = 0; kk < 4; kk++) {
                uint32_t pa_h[4], pa_l[4];
                {
                    float p00 = s[2*kk][0],   p01 = s[2*kk][1];
                    float p10 = s[2*kk][2],   p11 = s[2*kk][3];
                    float p20 = s[2*kk+1][0], p21 = s[2*kk+1][1];
                    float p30 = s[2*kk+1][2], p31 = s[2*kk+1][3];
                    pa_h[0] = pack_h2(p00, p01);
                    pa_h[1] = pack_h2(p10, p11);
                    pa_h[2] = pack_h2(p20, p21);
                    pa_h[3] = pack_h2(p30, p31);
                    __half2 t;
                    t = *(__half2*)&pa_h[0];
                    pa_l[0] = pack_h2(p00 - __half2float(t.x), p01 - __half2float(t.y));
                    t = *(__half2*)&pa_h[1];
                    pa_l[1] = pack_h2(p10 - __half2float(t.x), p11 - __half2float(t.y));
                    t = *(__half2*)&pa_h[2];
                    pa_l[2] = pack_h2(p20 - __half2float(t.x), p21 - __half2float(t.y));
                    t = *(__half2*)&pa_h[3];
                    pa_l[3] = pack_h2(p30 - __half2float(t.x), p31 - __half2float(t.y));
                }
                uint32_t vh[8][2];
#pragma unroll
                for (int p = 0; p < 4; p++) {
                    uint32_t off = (uint32_t)((kk * 16 + v_row) * (AST * 2) + (p * 16 + v_col) * 2);
                    uint32_t r4[4];
                    ldsm_x4_t(r4, sVH + off);
                    vh[p*2][0] = r4[0]; vh[p*2][1] = r4[1];
                    vh[p*2+1][0] = r4[2]; vh[p*2+1][1] = r4[3];
                }
#pragma unroll
                for (int ni = 0; ni < 8; ni++) {
                    mma16816(o[ni], pa_h, vh[ni]);
                    mma16816(o[ni], pa_l, vh[ni]);
                }
            }
        }
        __syncthreads();
    }

    const float inv0 = 1.0f / l0, inv1 = 1.0f / l1;
    const int gr = grow0 + wr + lr;
    const int gcb = h * DH + qc * 2;
#pragma unroll
    for (int ni = 0; ni < 8; ni++) {
        float v0 = o[ni][0] * inv0, v1 = o[ni][1] * inv0;
        float v2 = o[ni][2] * inv1, v3 = o[ni][3] * inv1;
        size_t i0 = (size_t)gr * NX + gcb + ni * 8;
        size_t i1 = (size_t)(gr + 8) * NX + gcb + ni * 8;
        *(uint32_t*)(ohi_ + i0) = pack_h2(v0, v1);
        *(uint32_t*)(ohi_ + i1) = pack_h2(v2, v3);
    }
}

// =====================================================================
// weight transpose (fp16): Wt[n][k] = fp16(W[k][n])
// =====================================================================
__global__ __launch_bounds__(256) void tsplit_kernel(
    const float* __restrict__ W, __half* __restrict__ hi, int K, int N)
{
    __shared__ float t[32][33];
    const int n0 = blockIdx.x * 32, k0 = blockIdx.y * 32;
    const int tx = threadIdx.x & 31, ty = threadIdx.x >> 5;
#pragma unroll
    for (int i = 0; i < 32; i += 8)
        t[ty + i][tx] = W[(size_t)(k0 + ty + i) * N + n0 + tx];
    __syncthreads();
#pragma unroll
    for (int i = 0; i < 32; i += 8) {
        float v = t[tx][ty + i];
        hi[(size_t)(n0 + ty + i) * K + k0 + tx] = __float2half_rn(v);
    }
}

// fp16 convert (hi only)
__global__ __launch_bounds__(256) void split_kernel(
    const float* __restrict__ in, __half* __restrict__ hi, int n4)
{
    int i = blockIdx.x * blockDim.x + threadIdx.x;
    if (i >= n4) return;
    float4 v = *(const float4*)(in + i * 4);
    __half2 p0 = __floats2half2_rn(v.x, v.y);
    __half2 p1 = __floats2half2_rn(v.z, v.w);
    *(__half2*)(hi + i * 4) = p0;
    *(__half2*)(hi + i * 4 + 2) = p1;
}

// =====================================================================
// LayerNorm (additive, faithful to source bug) + optional fp16 out (hi only)
// =====================================================================
__global__ __launch_bounds__(256) void ln_kernel(
    const float* __restrict__ in1, const float* __restrict__ in2,
    const float* __restrict__ g, const float* __restrict__ bb,
    float* __restrict__ out, __half* __restrict__ ohi)
{
    __shared__ float buf[NX];
    __shared__ float wsum[8], wsum2[8];

    const int row = blockIdx.x;
    const int tid = threadIdx.x;
    const int lane = tid & 31;
    const int wrp = tid >> 5;
    const size_t base = (size_t)row * NX;

    float s = 0.0f, s2 = 0.0f;
#pragma unroll
    for (int k = 0; k < 3; k++) {
        int i = tid + k * 256;
        float v = in1[base + i] + in2[base + i];
        buf[i] = v;
        s += v; s2 += v * v;
    }
#pragma unroll
    for (int off = 16; off > 0; off >>= 1) {
        s  += __shfl_xor_sync(0xffffffffu, s,  off);
        s2 += __shfl_xor_sync(0xffffffffu, s2, off);
    }
    if (lane == 0) { wsum[wrp] = s; wsum2[wrp] = s2; }
    __syncthreads();
    if (wrp == 0) {
        float a = (lane < 8) ? wsum[lane] : 0.0f;
        float a2 = (lane < 8) ? wsum2[lane] : 0.0f;
#pragma unroll
        for (int off = 4; off > 0; off >>= 1) {
            a  += __shfl_xor_sync(0xffffffffu, a,  off);
            a2 += __shfl_xor_sync(0xffffffffu, a2, off);
        }
        if (lane == 0) { wsum[0] = a; wsum2[0] = a2; }
    }
    __syncthreads();
    const float u = wsum[0] * (1.0f / NX);
    const float var = wsum2[0] * (1.0f / NX) - u * u;
    const float rstd = rsqrtf(var + EPS);
#pragma unroll
    for (int k = 0; k < 3; k++) {
        int i = tid + k * 256;
        float v = g[i] + (buf[i] - u) * rstd + bb[i];
        out[base + i] = v;
        if (ohi) ohi[base + i] = __float2half_rn(v);
    }
}

// =====================================================================
extern "C" void kernel_launch(void* const* d_in, const int* in_sizes, int n_in,
                              void* d_out, int out_size)
{
    const float* x      = (const float*)d_in[0];
    const float* w_attn = (const float*)d_in[1];
    const float* b_attn = (const float*)d_in[2];
    const float* w_proj = (const float*)d_in[3];
    const float* b_proj = (const float*)d_in[4];
    const float* ln1_g  = (const float*)d_in[5];
    const float* ln1_b  = (const float*)d_in[6];
    const float* w_fc   = (const float*)d_in[7];
    const float* b_fc   = (const float*)d_in[8];
    const float* w_fc2  = (const float*)d_in[9];
    const float* b_fc2  = (const float*)d_in[10];
    const float* ln2_g  = (const float*)d_in[11];
    const float* ln2_b  = (const float*)d_in[12];
    float* out = (float*)d_out;

    float *nbuf, *tmp;
    __half *ahi, *hhi, *hlo, *whi;
    cudaGetSymbolAddress((void**)&nbuf, g_n);
    cudaGetSymbolAddress((void**)&tmp,  g_tmp);
    cudaGetSymbolAddress((void**)&ahi,  g_ahi);
    cudaGetSymbolAddress((void**)&hhi,  g_hhi);
    cudaGetSymbolAddress((void**)&hlo,  g_hlo);
    cudaGetSymbolAddress((void**)&whi,  g_whi);

    static int smem_set = 0;
    if (!smem_set) {
        cudaFuncSetAttribute(gemm_tc_kernel,
                             cudaFuncAttributeMaxDynamicSharedMemorySize, GEMM_DSMEM);
        cudaFuncSetAttribute(attn_mma_kernel,
                             cudaFuncAttributeMaxDynamicSharedMemorySize, ATTN_DSMEM);
        smem_set = 1;
    }

    // --- weight prep (fp16) ---
    tsplit_kernel<<<dim3(3 * NX / 32, NX / 32), 256>>>(w_attn, whi + WOFF_ATTN, NX, 3 * NX);
    tsplit_kernel<<<dim3(NX / 32, NX / 32),     256>>>(w_proj, whi + WOFF_PROJ, NX, NX);
    tsplit_kernel<<<dim3(4 * NX / 32, NX / 32), 256>>>(w_fc,   whi + WOFF_FC,   NX, 4 * NX);
    tsplit_kernel<<<dim3(NX / 32, 4 * NX / 32), 256>>>(w_fc2,  whi + WOFF_FC2,  4 * NX, NX);

    // --- x -> fp16 ---
    split_kernel<<<(MROWS * NX / 4 + 255) / 256, 256>>>(x, ahi, MROWS * NX / 4);

    // 1. qkv = x @ w_attn + b_attn  -> fp16 hi (all) + lo (Q,K cols only)
    gemm_tc_kernel<<<dim3(3 * NX / 128, MROWS / 128), 256, GEMM_DSMEM>>>(
        ahi, whi + WOFF_ATTN, b_attn, nullptr, hhi, hlo,
        MROWS, 3 * NX, NX, 0, 2 * NX);

    // 2. attention (QK 3-term, PV 2-term)
    attn_mma_kernel<<<dim3(NCTX / 128, NHEAD, BATCH), 256, ATTN_DSMEM>>>(
        hhi, hlo, ahi);

    // 3. proj = attn @ w_proj + b_proj -> tmp fp32
    gemm_tc_kernel<<<dim3(NX / 128, MROWS / 128), 256, GEMM_DSMEM>>>(
        ahi, whi + WOFF_PROJ, b_proj, tmp, nullptr, nullptr,
        MROWS, NX, NX, 0, 0);

    // 4. n = LN(x + proj) -> nbuf fp32 + ahi fp16
    ln_kernel<<<MROWS, 256>>>(x, tmp, ln1_g, ln1_b, nbuf, ahi);

    // 5. h = relu(n @ w_fc + b_fc) -> hhi fp16 only
    gemm_tc_kernel<<<dim3(4 * NX / 128, MROWS / 128), 256, GEMM_DSMEM>>>(
        ahi, whi + WOFF_FC, b_fc, nullptr, hhi, nullptr,
        MROWS, 4 * NX, NX, 1, 0);

    // 6. m = h @ w_fc2 + b_fc2 -> tmp
    gemm_tc_kernel<<<dim3(NX / 128, MROWS / 128), 256, GEMM_DSMEM>>>(
        hhi, whi + WOFF_FC2, b_fc2, tmp, nullptr, nullptr,
        MROWS, NX, 4 * NX, 0, 0);

    // 7. out = LN(n + m)
    ln_kernel<<<MROWS, 256>>>(nbuf, tmp, ln2_g, ln2_b, out, nullptr);
}